// round 2
// baseline (speedup 1.0000x reference)
#include <cuda_runtime.h>
#include <float.h>
#include <stdint.h>

#define D_MODEL  4096
#define D_SAE    16384
#define K_SPARSE 64
#define K_CAND   72
#define N_TOKENS 8192

// ---- device scratch (no allocation allowed; static __device__ globals) ----
__device__ float g_WdT[(size_t)D_SAE * D_MODEL];   // W_dec transposed: [f][d], 256 MB
__device__ float g_tv[N_TOKENS * K_SPARSE];        // final top-k values (fp32 pre)
__device__ int   g_ti[N_TOKENS * K_SPARSE];        // final top-k indices
__device__ int   g_cand[N_TOKENS * K_CAND];        // top-72 candidate indices (fp32 rank)

// ---------------- double-float helpers (error-free transforms) -------------
__device__ __forceinline__ void two_sum(float a, float b, float& s, float& e)
{
    s = a + b;
    float bb = s - a;
    e = (a - (s - bb)) + (b - bb);
}
__device__ __forceinline__ void df_add(float& h1, float& l1, float h2, float l2)
{
    float s, e;
    two_sum(h1, h2, s, e);
    float lo = l1 + l2 + e;
    float hn = s + lo;          // renormalize
    l1 = lo - (hn - s);
    h1 = hn;
}

// ======================================================================
// Kernel 1: transpose W_dec (D_MODEL x D_SAE) -> g_WdT (D_SAE x D_MODEL)
// ======================================================================
__global__ void transpose_kernel(const float* __restrict__ in)
{
    __shared__ float tile[32][33];
    int x  = blockIdx.x * 32 + threadIdx.x;   // f
    int y0 = blockIdx.y * 32 + threadIdx.y;   // d
    #pragma unroll
    for (int j = 0; j < 32; j += 8)
        tile[threadIdx.y + j][threadIdx.x] = in[(size_t)(y0 + j) * D_SAE + x];
    __syncthreads();
    int x2 = blockIdx.y * 32 + threadIdx.x;   // d
    int y2 = blockIdx.x * 32 + threadIdx.y;   // f
    #pragma unroll
    for (int j = 0; j < 32; j += 8)
        g_WdT[(size_t)(y2 + j) * D_MODEL + x2] = tile[threadIdx.x][threadIdx.y + j];
}

// ======================================================================
// Kernel 2: SGEMM (NT): pre[n,f] = sum_d x[n,d]*W_enc[f,d] + b_enc[f]
// ======================================================================
__global__ __launch_bounds__(256, 2)
void sgemm_nt_kernel(const float* __restrict__ A, const float* __restrict__ B,
                     const float* __restrict__ bias, float* __restrict__ C)
{
    constexpr int BM = 128, BN = 128, BK = 8, TM = 8, TN = 8;
    constexpr int K = D_MODEL, N = D_SAE;

    __shared__ float As[BK][BM];
    __shared__ float Bs[BK][BN];

    const int tid = threadIdx.x;
    const int bm = blockIdx.y * BM;
    const int bn = blockIdx.x * BN;

    const int lRow = tid >> 1;
    const int lCol = (tid & 1) << 2;
    const float* Ap = A + (size_t)(bm + lRow) * K + lCol;
    const float* Bp = B + (size_t)(bn + lRow) * K + lCol;

    const int tm = (tid >> 4) * TM;
    const int tn = (tid & 15) * TN;

    float acc[TM][TN] = {};

    for (int k0 = 0; k0 < K; k0 += BK) {
        float4 a4 = *reinterpret_cast<const float4*>(Ap);
        float4 b4 = *reinterpret_cast<const float4*>(Bp);
        Ap += BK; Bp += BK;
        As[lCol + 0][lRow] = a4.x; As[lCol + 1][lRow] = a4.y;
        As[lCol + 2][lRow] = a4.z; As[lCol + 3][lRow] = a4.w;
        Bs[lCol + 0][lRow] = b4.x; Bs[lCol + 1][lRow] = b4.y;
        Bs[lCol + 2][lRow] = b4.z; Bs[lCol + 3][lRow] = b4.w;
        __syncthreads();

        #pragma unroll
        for (int kk = 0; kk < BK; kk++) {
            float4 a0 = *reinterpret_cast<const float4*>(&As[kk][tm]);
            float4 a1 = *reinterpret_cast<const float4*>(&As[kk][tm + 4]);
            float4 b0 = *reinterpret_cast<const float4*>(&Bs[kk][tn]);
            float4 b1 = *reinterpret_cast<const float4*>(&Bs[kk][tn + 4]);
            float ar[TM] = {a0.x, a0.y, a0.z, a0.w, a1.x, a1.y, a1.z, a1.w};
            float br[TN] = {b0.x, b0.y, b0.z, b0.w, b1.x, b1.y, b1.z, b1.w};
            #pragma unroll
            for (int i = 0; i < TM; i++)
                #pragma unroll
                for (int j = 0; j < TN; j++)
                    acc[i][j] += ar[i] * br[j];
        }
        __syncthreads();
    }

    float bv[TN];
    #pragma unroll
    for (int j = 0; j < TN; j++) bv[j] = bias[bn + tn + j];

    #pragma unroll
    for (int i = 0; i < TM; i++) {
        float* crow = C + (size_t)(bm + tm + i) * N + bn + tn;
        float4 o0 = make_float4(acc[i][0] + bv[0], acc[i][1] + bv[1],
                                acc[i][2] + bv[2], acc[i][3] + bv[3]);
        float4 o1 = make_float4(acc[i][4] + bv[4], acc[i][5] + bv[5],
                                acc[i][6] + bv[6], acc[i][7] + bv[7]);
        *reinterpret_cast<float4*>(crow)     = o0;
        *reinterpret_cast<float4*>(crow + 4) = o1;
    }
}

// ======================================================================
// Kernel 3: top-72 candidates per token (fp32 ranking, wide margin).
//   One CTA per token, 256 threads. Also zero-fills sparse_acts row.
// ======================================================================
__global__ void topk_kernel(const float* __restrict__ pre,
                            float* __restrict__ sparse)
{
    extern __shared__ float sm[];
    float* vals = sm;                                // D_SAE floats
    float* rv   = sm + D_SAE;                        // 256 floats
    int*   ri   = reinterpret_cast<int*>(sm + D_SAE + 256);  // 256 ints

    const int n = blockIdx.x;
    const int t = threadIdx.x;
    const float* row = pre + (size_t)n * D_SAE;
    float* srow = sparse + (size_t)n * D_SAE;

    for (int i = t; i < D_SAE; i += 256) {
        vals[i] = row[i];
        srow[i] = 0.0f;
    }
    __syncthreads();

    float myV = -FLT_MAX;
    int   myI = 0x7fffffff;
    bool rescan = true;

    for (int it = 0; it < K_CAND; it++) {
        if (rescan) {
            myV = -FLT_MAX; myI = 0x7fffffff;
            #pragma unroll 8
            for (int i = 0; i < D_SAE / 256; i++) {
                int idx = i * 256 + t;
                float v = vals[idx];
                if (v > myV) { myV = v; myI = idx; }
            }
            rescan = false;
        }
        rv[t] = myV; ri[t] = myI;
        __syncthreads();
        #pragma unroll
        for (int s = 128; s > 0; s >>= 1) {
            if (t < s) {
                float ov = rv[t + s]; int oi = ri[t + s];
                if (ov > rv[t] || (ov == rv[t] && oi < ri[t])) { rv[t] = ov; ri[t] = oi; }
            }
            __syncthreads();
        }
        int wi = ri[0];
        if (t == 0) {
            g_cand[n * K_CAND + it] = wi;
            vals[wi] = -FLT_MAX;
        }
        __syncthreads();
        if ((wi & 255) == t) rescan = true;
    }
}

// ======================================================================
// Kernel 4: refine + select. One CTA per token, 256 threads.
//   Recompute the 72 candidate dot products in double-float (<<1 ulp),
//   rank in extended precision (ties -> lowest index, matching
//   jax.lax.top_k), select top-64, scatter fp32 pre values.
// ======================================================================
__global__ __launch_bounds__(256)
void refine_kernel(const float* __restrict__ x,
                   const float* __restrict__ W_enc,
                   const float* __restrict__ b_enc,
                   const float* __restrict__ pre,
                   float* __restrict__ sparse)
{
    __shared__ float xs[D_MODEL];
    __shared__ float rh[256];
    __shared__ float rl[256];
    __shared__ float cvh[K_CAND];
    __shared__ float cvl[K_CAND];
    __shared__ int   cidx[K_CAND];

    const int n = blockIdx.x;
    const int t = threadIdx.x;

    // load x row into smem
    #pragma unroll
    for (int j = 0; j < D_MODEL / 256; j++)
        xs[j * 256 + t] = x[(size_t)n * D_MODEL + j * 256 + t];
    if (t < K_CAND) cidx[t] = g_cand[n * K_CAND + t];
    __syncthreads();

    // per-candidate compensated dot product
    for (int c = 0; c < K_CAND; c++) {
        const int f = cidx[c];
        const float* wrow = W_enc + (size_t)f * D_MODEL;
        float hi = 0.0f, lo = 0.0f;
        #pragma unroll
        for (int j = 0; j < D_MODEL / 256; j++) {
            int k = j * 256 + t;
            float a = xs[k];
            float b = wrow[k];
            float p  = a * b;
            float ep = fmaf(a, b, -p);      // exact product error
            float s, e;
            two_sum(hi, p, s, e);
            hi = s;
            lo += (e + ep);
        }
        rh[t] = hi; rl[t] = lo;
        __syncthreads();
        #pragma unroll
        for (int s = 128; s > 0; s >>= 1) {
            if (t < s) {
                float h = rh[t], l = rl[t];
                df_add(h, l, rh[t + s], rl[t + s]);
                rh[t] = h; rl[t] = l;
            }
            __syncthreads();
        }
        if (t == 0) {
            float h = rh[0], l = rl[0];
            df_add(h, l, b_enc[f], 0.0f);   // add encoder bias
            cvh[c] = h; cvl[c] = l;
        }
        __syncthreads();
    }

    // extended-precision ranking: beats = exact rank (0..71), unique
    if (t < K_CAND) {
        float hI = cvh[t], lI = cvl[t];
        int   iI = cidx[t];
        int beats = 0;
        for (int j = 0; j < K_CAND; j++) {
            float hJ = cvh[j], lJ = cvl[j];
            int   iJ = cidx[j];
            bool gt = (hJ > hI) || (hJ == hI && (lJ > lI || (lJ == lI && iJ < iI)));
            beats += gt ? 1 : 0;
        }
        if (beats < K_SPARSE) {
            float v = pre[(size_t)n * D_SAE + iI];   // fp32 pre value (consistent)
            sparse[(size_t)n * D_SAE + iI] = v;
            g_tv[n * K_SPARSE + beats] = v;
            g_ti[n * K_SPARSE + beats] = iI;
        }
    }
}

// ======================================================================
// Kernel 5: sparse decode. One CTA per token, 256 threads, 16 floats each.
// ======================================================================
__global__ __launch_bounds__(256)
void decode_kernel(const float* __restrict__ b_dec, float* __restrict__ recon)
{
    __shared__ float sval[K_SPARSE];
    __shared__ int   sidx[K_SPARSE];
    const int n = blockIdx.x;
    const int t = threadIdx.x;
    if (t < K_SPARSE) {
        sval[t] = g_tv[n * K_SPARSE + t];
        sidx[t] = g_ti[n * K_SPARSE + t];
    }
    __syncthreads();

    float4 acc[4];
    #pragma unroll
    for (int c = 0; c < 4; c++)
        acc[c] = *reinterpret_cast<const float4*>(b_dec + c * 1024 + t * 4);

    #pragma unroll 4
    for (int j = 0; j < K_SPARSE; j++) {
        const float v = sval[j];
        const float* wrow = g_WdT + (size_t)sidx[j] * D_MODEL;
        #pragma unroll
        for (int c = 0; c < 4; c++) {
            float4 w = *reinterpret_cast<const float4*>(wrow + c * 1024 + t * 4);
            acc[c].x += v * w.x; acc[c].y += v * w.y;
            acc[c].z += v * w.z; acc[c].w += v * w.w;
        }
    }
    float* orow = recon + (size_t)n * D_MODEL;
    #pragma unroll
    for (int c = 0; c < 4; c++)
        *reinterpret_cast<float4*>(orow + c * 1024 + t * 4) = acc[c];
}

// ======================================================================
// kernel_launch
// ======================================================================
extern "C" void kernel_launch(void* const* d_in, const int* in_sizes, int n_in,
                              void* d_out, int out_size)
{
    const float* x     = (const float*)d_in[0];
    const float* W_enc = (const float*)d_in[1];
    const float* b_enc = (const float*)d_in[2];
    const float* W_dec = (const float*)d_in[3];
    const float* b_dec = (const float*)d_in[4];

    float* out    = (float*)d_out;
    float* recon  = out;
    float* sparse = out + (size_t)N_TOKENS * D_MODEL;
    float* pre    = sparse + (size_t)N_TOKENS * D_SAE;

    // 1) transpose W_dec for coalesced sparse-row gathers
    {
        dim3 tb(32, 8), tg(D_SAE / 32, D_MODEL / 32);
        transpose_kernel<<<tg, tb>>>(W_dec);
    }

    // 2) encoder GEMM -> pre_acts (fp32)
    {
        dim3 grid(D_SAE / 128, N_TOKENS / 128);
        sgemm_nt_kernel<<<grid, 256>>>(x, W_enc, b_enc, pre);
    }

    // 3) top-72 candidates (fp32 rank) + zero-fill sparse_acts
    {
        int smem = D_SAE * (int)sizeof(float) + 256 * (int)sizeof(float) + 256 * (int)sizeof(int);
        cudaFuncSetAttribute(topk_kernel, cudaFuncAttributeMaxDynamicSharedMemorySize, smem);
        topk_kernel<<<N_TOKENS, 256, smem>>>(pre, sparse);
    }

    // 4) double-float refinement -> exact top-64 selection + scatter
    refine_kernel<<<N_TOKENS, 256>>>(x, W_enc, b_enc, pre, sparse);

    // 5) sparse decode -> reconstruction
    decode_kernel<<<N_TOKENS, 256>>>(b_dec, recon);
}

// round 14
// speedup vs baseline: 4.4311x; 4.4311x over previous
#include <cuda_runtime.h>
#include <cuda_fp16.h>
#include <float.h>
#include <stdint.h>

#define D_MODEL  4096
#define D_SAE    16384
#define K_SPARSE 64
#define K_CAND   72
#define N_TOKENS 8192

// GEMM tiling (mma.sync path — sm_103 base ISA only, no 'a' features)
#define BM 128
#define BN 128
#define BK 32
#define KITERS (D_MODEL / BK)   // 128
#define STAGE_SZ 16384          // A 8KB + B 8KB per stage
#define NSTAGES 4

// ---- device scratch (no allocation allowed; static __device__ globals) ----
__device__ float  g_WdT[(size_t)D_SAE * D_MODEL];           // W_dec^T, 256 MB
__device__ float  g_tv[N_TOKENS * K_SPARSE];
__device__ int    g_ti[N_TOKENS * K_SPARSE];
__device__ int    g_cand[N_TOKENS * K_CAND];
__device__ __half g_xh[(size_t)N_TOKENS * D_MODEL];         // x in fp16, 64 MB
__device__ __half g_wh[(size_t)D_SAE * D_MODEL];            // W_enc in fp16, 128 MB

// =================== helpers ==============
__device__ __forceinline__ uint32_t smem_to_u32(const void* p) {
    uint32_t a;
    asm("{ .reg .u64 t; cvta.to.shared.u64 t, %1; cvt.u32.u64 %0, t; }" : "=r"(a) : "l"(p));
    return a;
}

#define LDMX4(r0, r1, r2, r3, addr) \
    asm volatile("ldmatrix.sync.aligned.m8n8.x4.shared.b16 {%0,%1,%2,%3}, [%4];" \
        : "=r"(r0), "=r"(r1), "=r"(r2), "=r"(r3) : "r"(addr))

#define MMA16816(d, a, b) \
    asm volatile("mma.sync.aligned.m16n8k16.row.col.f32.f16.f16.f32 " \
        "{%0,%1,%2,%3}, {%4,%5,%6,%7}, {%8,%9}, {%0,%1,%2,%3};" \
        : "+f"((d)[0]), "+f"((d)[1]), "+f"((d)[2]), "+f"((d)[3]) \
        : "r"((a)[0]), "r"((a)[1]), "r"((a)[2]), "r"((a)[3]), \
          "r"((b)[0]), "r"((b)[1]))

// ---------------- double-float helpers (error-free transforms) -------------
__device__ __forceinline__ void two_sum(float a, float b, float& s, float& e)
{
    s = a + b;
    float bb = s - a;
    e = (a - (s - bb)) + (b - bb);
}
__device__ __forceinline__ void df_add(float& h1, float& l1, float h2, float l2)
{
    float s, e;
    two_sum(h1, h2, s, e);
    float lo = l1 + l2 + e;
    float hn = s + lo;
    l1 = lo - (hn - s);
    h1 = hn;
}

// ======================================================================
// Kernel 0a/0b: fp32 -> fp16 conversion (4 elems/thread)
// ======================================================================
__global__ void cvt_x_kernel(const float* __restrict__ src)
{
    size_t i = ((size_t)blockIdx.x * 256 + threadIdx.x) * 4;
    float4 v = *reinterpret_cast<const float4*>(src + i);
    reinterpret_cast<__half2*>(g_xh + i)[0] = __floats2half2_rn(v.x, v.y);
    reinterpret_cast<__half2*>(g_xh + i)[1] = __floats2half2_rn(v.z, v.w);
}
__global__ void cvt_w_kernel(const float* __restrict__ src)
{
    size_t i = ((size_t)blockIdx.x * 256 + threadIdx.x) * 4;
    float4 v = *reinterpret_cast<const float4*>(src + i);
    reinterpret_cast<__half2*>(g_wh + i)[0] = __floats2half2_rn(v.x, v.y);
    reinterpret_cast<__half2*>(g_wh + i)[1] = __floats2half2_rn(v.z, v.w);
}

// ======================================================================
// Kernel 1: transpose W_dec (D_MODEL x D_SAE) -> g_WdT (D_SAE x D_MODEL)
// ======================================================================
__global__ void transpose_kernel(const float* __restrict__ in)
{
    __shared__ float tile[32][33];
    int x  = blockIdx.x * 32 + threadIdx.x;
    int y0 = blockIdx.y * 32 + threadIdx.y;
    #pragma unroll
    for (int j = 0; j < 32; j += 8)
        tile[threadIdx.y + j][threadIdx.x] = in[(size_t)(y0 + j) * D_SAE + x];
    __syncthreads();
    int x2 = blockIdx.y * 32 + threadIdx.x;
    int y2 = blockIdx.x * 32 + threadIdx.y;
    #pragma unroll
    for (int j = 0; j < 32; j += 8)
        g_WdT[(size_t)(y2 + j) * D_MODEL + x2] = tile[threadIdx.x][threadIdx.y + j];
}

// ======================================================================
// Kernel 2: encoder GEMM, fp16 mma.sync, fp32 accum.
//   pre[n,f] = sum_d xh[n,d]*wh[f,d] + b_enc[f]
//   CTA 128x128, 4 warps (2x2) of 64x64, BK=32, 4-stage cp.async ring.
//   smem tile layout: row-major [128][32] half, 64B rows, xor swizzle:
//   chunk16' = chunk16 ^ ((row>>1)&3)  -> conflict-free ldmatrix.
// ======================================================================
__device__ __forceinline__ void load_stage(uint32_t sb, size_t bm, size_t bn,
                                           int k0, int tid)
{
    #pragma unroll
    for (int q = 0; q < 8; q++) {
        int c = q * 128 + tid;          // 0..1023; A: [0,512), B: [512,1024)
        int isB = c >> 9;
        int r   = (c >> 2) & 127;
        int c16 = c & 3;
        const __half* src = (isB ? g_wh + (bn + r) * (size_t)D_MODEL
                                 : g_xh + (bm + r) * (size_t)D_MODEL)
                            + (k0 + c16 * 8);
        uint32_t dst = sb + (isB << 13) + r * 64 + ((c16 ^ ((r >> 1) & 3)) << 4);
        asm volatile("cp.async.cg.shared.global [%0], [%1], 16;" :: "r"(dst), "l"(src));
    }
}

__global__ __launch_bounds__(128, 2)
void enc_gemm_kernel(const float* __restrict__ bias, float* __restrict__ C)
{
    extern __shared__ char smem[];
    const uint32_t sb0 = smem_to_u32(smem);
    const int tid  = threadIdx.x;
    const int lane = tid & 31;
    const int wid  = tid >> 5;
    const int wm   = wid >> 1;           // 0..1
    const int wn   = wid & 1;            // 0..1

    // m-panel swizzled rasterization: 8 m-tiles per panel, sweep all n (L2 reuse)
    const int bid = blockIdx.x;
    const int mt  = (bid >> 10) * 8 + (bid & 7);   // 0..63
    const int nt  = (bid >> 3) & 127;              // 0..127
    const size_t bm = (size_t)mt * BM;
    const size_t bn = (size_t)nt * BN;

    // per-lane ldmatrix row/xor precompute
    // A tiles (m16k16 per x4): lanes 0-7: m0-7@k0, 8-15: m8-15@k0, 16-23: m0-7@k8, 24-31: m8-15@k8
    const int rA = wm * 64 + ((lane >> 3) & 1) * 8 + (lane & 7);
    const int xA = (rA >> 1) & 3;        // invariant under +16 row steps
    const int cA = (lane >> 4);          // k-half within chunk pair
    // B tiles (n16k16 per x4): lanes 0-7: n0-7@k0, 8-15: n0-7@k8, 16-23: n8-15@k0, 24-31: n8-15@k8
    const int rB = wn * 64 + ((lane >> 4) & 1) * 8 + (lane & 7);
    const int xB = (rB >> 1) & 3;
    const int cB = (lane >> 3) & 1;

    float acc[4][8][4] = {};

    // prologue: fill 3 stages
    #pragma unroll
    for (int s = 0; s < 3; s++) {
        load_stage(sb0 + s * STAGE_SZ, bm, bn, s * BK, tid);
        asm volatile("cp.async.commit_group;" ::: "memory");
    }

    for (int i = 0; i < KITERS; i++) {
        asm volatile("cp.async.wait_group 2;" ::: "memory");
        __syncthreads();
        // prefetch stage i+3 (buffer (i-1)%4, all warps past it per barrier above)
        if (i + 3 < KITERS)
            load_stage(sb0 + ((i + 3) & 3) * STAGE_SZ, bm, bn, (i + 3) * BK, tid);
        asm volatile("cp.async.commit_group;" ::: "memory");   // possibly-empty group keeps count uniform

        const uint32_t sb = sb0 + (i & 3) * STAGE_SZ;
        #pragma unroll
        for (int h = 0; h < 2; h++) {
            uint32_t a[4][4], b[8][2];
            #pragma unroll
            for (int mf = 0; mf < 4; mf++) {
                uint32_t ad = sb + (rA + mf * 16) * 64 + (((h * 2 + cA) ^ xA) << 4);
                LDMX4(a[mf][0], a[mf][1], a[mf][2], a[mf][3], ad);
            }
            #pragma unroll
            for (int nf = 0; nf < 4; nf++) {
                uint32_t bd = sb + 8192 + (rB + nf * 16) * 64 + (((h * 2 + cB) ^ xB) << 4);
                LDMX4(b[nf * 2][0], b[nf * 2][1], b[nf * 2 + 1][0], b[nf * 2 + 1][1], bd);
            }
            #pragma unroll
            for (int mf = 0; mf < 4; mf++)
                #pragma unroll
                for (int nf = 0; nf < 8; nf++)
                    MMA16816(acc[mf][nf], a[mf], b[nf]);
        }
    }

    // epilogue: direct register -> gmem with bias
    const int tr = lane >> 2;
    const int tc = (lane & 3) * 2;
    #pragma unroll
    for (int nf = 0; nf < 8; nf++) {
        const size_t col = bn + wn * 64 + nf * 8 + tc;
        const float bv0 = bias[col];
        const float bv1 = bias[col + 1];
        #pragma unroll
        for (int mf = 0; mf < 4; mf++) {
            const size_t row = bm + wm * 64 + mf * 16 + tr;
            float2 v0 = make_float2(acc[mf][nf][0] + bv0, acc[mf][nf][1] + bv1);
            float2 v1 = make_float2(acc[mf][nf][2] + bv0, acc[mf][nf][3] + bv1);
            *reinterpret_cast<float2*>(C + row * D_SAE + col)       = v0;
            *reinterpret_cast<float2*>(C + (row + 8) * D_SAE + col) = v1;
        }
    }
}

// ======================================================================
// Kernel 3: top-72 candidates per token (fp32 ranking, wide margin).
// ======================================================================
__global__ void topk_kernel(const float* __restrict__ pre,
                            float* __restrict__ sparse)
{
    extern __shared__ float sm[];
    float* vals = sm;
    float* rv   = sm + D_SAE;
    int*   ri   = reinterpret_cast<int*>(sm + D_SAE + 256);

    const int n = blockIdx.x;
    const int t = threadIdx.x;
    const float* row = pre + (size_t)n * D_SAE;
    float* srow = sparse + (size_t)n * D_SAE;

    for (int i = t; i < D_SAE; i += 256) {
        vals[i] = row[i];
        srow[i] = 0.0f;
    }
    __syncthreads();

    float myV = -FLT_MAX;
    int   myI = 0x7fffffff;
    bool rescan = true;

    for (int it = 0; it < K_CAND; it++) {
        if (rescan) {
            myV = -FLT_MAX; myI = 0x7fffffff;
            #pragma unroll 8
            for (int i = 0; i < D_SAE / 256; i++) {
                int idx = i * 256 + t;
                float v = vals[idx];
                if (v > myV) { myV = v; myI = idx; }
            }
            rescan = false;
        }
        rv[t] = myV; ri[t] = myI;
        __syncthreads();
        #pragma unroll
        for (int s = 128; s > 0; s >>= 1) {
            if (t < s) {
                float ov = rv[t + s]; int oi = ri[t + s];
                if (ov > rv[t] || (ov == rv[t] && oi < ri[t])) { rv[t] = ov; ri[t] = oi; }
            }
            __syncthreads();
        }
        int wi = ri[0];
        if (t == 0) {
            g_cand[n * K_CAND + it] = wi;
            vals[wi] = -FLT_MAX;
        }
        __syncthreads();
        if ((wi & 255) == t) rescan = true;
    }
}

// ======================================================================
// Kernel 4: refine + select (double-float exact ranking of 72 candidates)
// ======================================================================
__global__ __launch_bounds__(256)
void refine_kernel(const float* __restrict__ x,
                   const float* __restrict__ W_enc,
                   const float* __restrict__ b_enc,
                   const float* __restrict__ pre,
                   float* __restrict__ sparse)
{
    __shared__ float xs[D_MODEL];
    __shared__ float rh[256];
    __shared__ float rl[256];
    __shared__ float cvh[K_CAND];
    __shared__ float cvl[K_CAND];
    __shared__ int   cidx[K_CAND];

    const int n = blockIdx.x;
    const int t = threadIdx.x;

    #pragma unroll
    for (int j = 0; j < D_MODEL / 256; j++)
        xs[j * 256 + t] = x[(size_t)n * D_MODEL + j * 256 + t];
    if (t < K_CAND) cidx[t] = g_cand[n * K_CAND + t];
    __syncthreads();

    for (int c = 0; c < K_CAND; c++) {
        const int f = cidx[c];
        const float* wrow = W_enc + (size_t)f * D_MODEL;
        float hi = 0.0f, lo = 0.0f;
        #pragma unroll
        for (int j = 0; j < D_MODEL / 256; j++) {
            int k = j * 256 + t;
            float a = xs[k];
            float b = wrow[k];
            float p  = a * b;
            float ep = fmaf(a, b, -p);
            float s, e;
            two_sum(hi, p, s, e);
            hi = s;
            lo += (e + ep);
        }
        rh[t] = hi; rl[t] = lo;
        __syncthreads();
        #pragma unroll
        for (int s = 128; s > 0; s >>= 1) {
            if (t < s) {
                float h = rh[t], l = rl[t];
                df_add(h, l, rh[t + s], rl[t + s]);
                rh[t] = h; rl[t] = l;
            }
            __syncthreads();
        }
        if (t == 0) {
            float h = rh[0], l = rl[0];
            df_add(h, l, b_enc[f], 0.0f);
            cvh[c] = h; cvl[c] = l;
        }
        __syncthreads();
    }

    if (t < K_CAND) {
        float hI = cvh[t], lI = cvl[t];
        int   iI = cidx[t];
        int beats = 0;
        for (int j = 0; j < K_CAND; j++) {
            float hJ = cvh[j], lJ = cvl[j];
            int   iJ = cidx[j];
            bool gt = (hJ > hI) || (hJ == hI && (lJ > lI || (lJ == lI && iJ < iI)));
            beats += gt ? 1 : 0;
        }
        if (beats < K_SPARSE) {
            float v = pre[(size_t)n * D_SAE + iI];
            sparse[(size_t)n * D_SAE + iI] = v;
            g_tv[n * K_SPARSE + beats] = v;
            g_ti[n * K_SPARSE + beats] = iI;
        }
    }
}

// ======================================================================
// Kernel 5: sparse decode
// ======================================================================
__global__ __launch_bounds__(256)
void decode_kernel(const float* __restrict__ b_dec, float* __restrict__ recon)
{
    __shared__ float sval[K_SPARSE];
    __shared__ int   sidx[K_SPARSE];
    const int n = blockIdx.x;
    const int t = threadIdx.x;
    if (t < K_SPARSE) {
        sval[t] = g_tv[n * K_SPARSE + t];
        sidx[t] = g_ti[n * K_SPARSE + t];
    }
    __syncthreads();

    float4 acc[4];
    #pragma unroll
    for (int c = 0; c < 4; c++)
        acc[c] = *reinterpret_cast<const float4*>(b_dec + c * 1024 + t * 4);

    #pragma unroll 4
    for (int j = 0; j < K_SPARSE; j++) {
        const float v = sval[j];
        const float* wrow = g_WdT + (size_t)sidx[j] * D_MODEL;
        #pragma unroll
        for (int c = 0; c < 4; c++) {
            float4 w = *reinterpret_cast<const float4*>(wrow + c * 1024 + t * 4);
            acc[c].x += v * w.x; acc[c].y += v * w.y;
            acc[c].z += v * w.z; acc[c].w += v * w.w;
        }
    }
    float* orow = recon + (size_t)n * D_MODEL;
    #pragma unroll
    for (int c = 0; c < 4; c++)
        *reinterpret_cast<float4*>(orow + c * 1024 + t * 4) = acc[c];
}

// ======================================================================
// kernel_launch
// ======================================================================
extern "C" void kernel_launch(void* const* d_in, const int* in_sizes, int n_in,
                              void* d_out, int out_size)
{
    const float* x     = (const float*)d_in[0];
    const float* W_enc = (const float*)d_in[1];
    const float* b_enc = (const float*)d_in[2];
    const float* W_dec = (const float*)d_in[3];
    const float* b_dec = (const float*)d_in[4];

    float* out    = (float*)d_out;
    float* recon  = out;
    float* sparse = out + (size_t)N_TOKENS * D_MODEL;
    float* pre    = sparse + (size_t)N_TOKENS * D_SAE;

    // 0) fp16 conversions of x and W_enc
    cvt_x_kernel<<<(int)(((size_t)N_TOKENS * D_MODEL) / 1024), 256>>>(x);
    cvt_w_kernel<<<(int)(((size_t)D_SAE * D_MODEL) / 1024), 256>>>(W_enc);

    // 1) transpose W_dec for coalesced sparse-row gathers
    {
        dim3 tb(32, 8), tg(D_SAE / 32, D_MODEL / 32);
        transpose_kernel<<<tg, tb>>>(W_dec);
    }

    // 2) encoder GEMM (fp16 mma.sync, fp32 accum) -> pre_acts
    {
        int smem = NSTAGES * STAGE_SZ;   // 64 KB
        cudaFuncSetAttribute(enc_gemm_kernel, cudaFuncAttributeMaxDynamicSharedMemorySize, smem);
        int grid = (N_TOKENS / BM) * (D_SAE / BN);   // 64 * 128 = 8192
        enc_gemm_kernel<<<grid, 128, smem>>>(b_enc, pre);
    }

    // 3) top-72 candidates (fp16-GEMM rank, 170-sigma margin) + zero-fill sparse
    {
        int smem = D_SAE * (int)sizeof(float) + 256 * (int)sizeof(float) + 256 * (int)sizeof(int);
        cudaFuncSetAttribute(topk_kernel, cudaFuncAttributeMaxDynamicSharedMemorySize, smem);
        topk_kernel<<<N_TOKENS, 256, smem>>>(pre, sparse);
    }

    // 4) double-float refinement -> exact top-64 selection + scatter
    refine_kernel<<<N_TOKENS, 256>>>(x, W_enc, b_enc, pre, sparse);

    // 5) sparse decode -> reconstruction
    decode_kernel<<<N_TOKENS, 256>>>(b_dec, recon);
}

// round 15
// speedup vs baseline: 4.4348x; 1.0008x over previous
#include <cuda_runtime.h>
#include <cuda_fp16.h>
#include <float.h>
#include <stdint.h>

#define D_MODEL  4096
#define D_SAE    16384
#define K_SPARSE 64
#define K_CAND   72
#define N_TOKENS 8192

// GEMM tiling (mma.sync path — sm_103 base ISA only, no 'a' features)
#define BM 128
#define BN 128
#define BK 32
#define KITERS (D_MODEL / BK)   // 128
#define STAGE_SZ 16384          // A 8KB + B 8KB per stage
#define NSTAGES 4

// ---- device scratch (no allocation allowed; static __device__ globals) ----
__device__ float  g_WdT[(size_t)D_SAE * D_MODEL];           // W_dec^T, 256 MB
__device__ float  g_tv[N_TOKENS * K_SPARSE];
__device__ int    g_ti[N_TOKENS * K_SPARSE];
__device__ int    g_cand[N_TOKENS * K_CAND];
__device__ __half g_xh[(size_t)N_TOKENS * D_MODEL];         // x in fp16, 64 MB
__device__ __half g_wh[(size_t)D_SAE * D_MODEL];            // W_enc in fp16, 128 MB

// =================== helpers ==============
__device__ __forceinline__ uint32_t smem_to_u32(const void* p) {
    uint32_t a;
    asm("{ .reg .u64 t; cvta.to.shared.u64 t, %1; cvt.u32.u64 %0, t; }" : "=r"(a) : "l"(p));
    return a;
}

#define LDMX4(r0, r1, r2, r3, addr) \
    asm volatile("ldmatrix.sync.aligned.m8n8.x4.shared.b16 {%0,%1,%2,%3}, [%4];" \
        : "=r"(r0), "=r"(r1), "=r"(r2), "=r"(r3) : "r"(addr))

#define MMA16816(d, a, b) \
    asm volatile("mma.sync.aligned.m16n8k16.row.col.f32.f16.f16.f32 " \
        "{%0,%1,%2,%3}, {%4,%5,%6,%7}, {%8,%9}, {%0,%1,%2,%3};" \
        : "+f"((d)[0]), "+f"((d)[1]), "+f"((d)[2]), "+f"((d)[3]) \
        : "r"((a)[0]), "r"((a)[1]), "r"((a)[2]), "r"((a)[3]), \
          "r"((b)[0]), "r"((b)[1]))

// ---------------- double-float helpers (error-free transforms) -------------
__device__ __forceinline__ void two_sum(float a, float b, float& s, float& e)
{
    s = a + b;
    float bb = s - a;
    e = (a - (s - bb)) + (b - bb);
}
__device__ __forceinline__ void df_add(float& h1, float& l1, float h2, float l2)
{
    float s, e;
    two_sum(h1, h2, s, e);
    float lo = l1 + l2 + e;
    float hn = s + lo;
    l1 = lo - (hn - s);
    h1 = hn;
}

// ======================================================================
// Kernel 0a/0b: fp32 -> fp16 conversion (4 elems/thread)
// ======================================================================
__global__ void cvt_x_kernel(const float* __restrict__ src)
{
    size_t i = ((size_t)blockIdx.x * 256 + threadIdx.x) * 4;
    float4 v = *reinterpret_cast<const float4*>(src + i);
    reinterpret_cast<__half2*>(g_xh + i)[0] = __floats2half2_rn(v.x, v.y);
    reinterpret_cast<__half2*>(g_xh + i)[1] = __floats2half2_rn(v.z, v.w);
}
__global__ void cvt_w_kernel(const float* __restrict__ src)
{
    size_t i = ((size_t)blockIdx.x * 256 + threadIdx.x) * 4;
    float4 v = *reinterpret_cast<const float4*>(src + i);
    reinterpret_cast<__half2*>(g_wh + i)[0] = __floats2half2_rn(v.x, v.y);
    reinterpret_cast<__half2*>(g_wh + i)[1] = __floats2half2_rn(v.z, v.w);
}

// ======================================================================
// Kernel 1: transpose W_dec (D_MODEL x D_SAE) -> g_WdT (D_SAE x D_MODEL)
// ======================================================================
__global__ void transpose_kernel(const float* __restrict__ in)
{
    __shared__ float tile[32][33];
    int x  = blockIdx.x * 32 + threadIdx.x;
    int y0 = blockIdx.y * 32 + threadIdx.y;
    #pragma unroll
    for (int j = 0; j < 32; j += 8)
        tile[threadIdx.y + j][threadIdx.x] = in[(size_t)(y0 + j) * D_SAE + x];
    __syncthreads();
    int x2 = blockIdx.y * 32 + threadIdx.x;
    int y2 = blockIdx.x * 32 + threadIdx.y;
    #pragma unroll
    for (int j = 0; j < 32; j += 8)
        g_WdT[(size_t)(y2 + j) * D_MODEL + x2] = tile[threadIdx.x][threadIdx.y + j];
}

// ======================================================================
// Kernel 2: encoder GEMM, fp16 mma.sync, fp32 accum.
//   pre[n,f] = sum_d xh[n,d]*wh[f,d] + b_enc[f]
//   CTA 128x128, 4 warps (2x2) of 64x64, BK=32, 4-stage cp.async ring.
//   smem tile layout: row-major [128][32] half, 64B rows, xor swizzle:
//   chunk16' = chunk16 ^ ((row>>1)&3)  -> conflict-free ldmatrix.
// ======================================================================
__device__ __forceinline__ void load_stage(uint32_t sb, size_t bm, size_t bn,
                                           int k0, int tid)
{
    #pragma unroll
    for (int q = 0; q < 8; q++) {
        int c = q * 128 + tid;          // 0..1023; A: [0,512), B: [512,1024)
        int isB = c >> 9;
        int r   = (c >> 2) & 127;
        int c16 = c & 3;
        const __half* src = (isB ? g_wh + (bn + r) * (size_t)D_MODEL
                                 : g_xh + (bm + r) * (size_t)D_MODEL)
                            + (k0 + c16 * 8);
        uint32_t dst = sb + (isB << 13) + r * 64 + ((c16 ^ ((r >> 1) & 3)) << 4);
        asm volatile("cp.async.cg.shared.global [%0], [%1], 16;" :: "r"(dst), "l"(src));
    }
}

__global__ __launch_bounds__(128, 2)
void enc_gemm_kernel(const float* __restrict__ bias, float* __restrict__ C)
{
    extern __shared__ char smem[];
    const uint32_t sb0 = smem_to_u32(smem);
    const int tid  = threadIdx.x;
    const int lane = tid & 31;
    const int wid  = tid >> 5;
    const int wm   = wid >> 1;           // 0..1
    const int wn   = wid & 1;            // 0..1

    // m-panel swizzled rasterization: 8 m-tiles per panel, sweep all n (L2 reuse)
    const int bid = blockIdx.x;
    const int mt  = (bid >> 10) * 8 + (bid & 7);   // 0..63
    const int nt  = (bid >> 3) & 127;              // 0..127
    const size_t bm = (size_t)mt * BM;
    const size_t bn = (size_t)nt * BN;

    // per-lane ldmatrix row/xor precompute
    // A tiles (m16k16 per x4): lanes 0-7: m0-7@k0, 8-15: m8-15@k0, 16-23: m0-7@k8, 24-31: m8-15@k8
    const int rA = wm * 64 + ((lane >> 3) & 1) * 8 + (lane & 7);
    const int xA = (rA >> 1) & 3;        // invariant under +16 row steps
    const int cA = (lane >> 4);          // k-half within chunk pair
    // B tiles (n16k16 per x4): lanes 0-7: n0-7@k0, 8-15: n0-7@k8, 16-23: n8-15@k0, 24-31: n8-15@k8
    const int rB = wn * 64 + ((lane >> 4) & 1) * 8 + (lane & 7);
    const int xB = (rB >> 1) & 3;
    const int cB = (lane >> 3) & 1;

    float acc[4][8][4] = {};

    // prologue: fill 3 stages
    #pragma unroll
    for (int s = 0; s < 3; s++) {
        load_stage(sb0 + s * STAGE_SZ, bm, bn, s * BK, tid);
        asm volatile("cp.async.commit_group;" ::: "memory");
    }

    for (int i = 0; i < KITERS; i++) {
        asm volatile("cp.async.wait_group 2;" ::: "memory");
        __syncthreads();
        // prefetch stage i+3 (buffer (i-1)%4, all warps past it per barrier above)
        if (i + 3 < KITERS)
            load_stage(sb0 + ((i + 3) & 3) * STAGE_SZ, bm, bn, (i + 3) * BK, tid);
        asm volatile("cp.async.commit_group;" ::: "memory");   // possibly-empty group keeps count uniform

        const uint32_t sb = sb0 + (i & 3) * STAGE_SZ;
        #pragma unroll
        for (int h = 0; h < 2; h++) {
            uint32_t a[4][4], b[8][2];
            #pragma unroll
            for (int mf = 0; mf < 4; mf++) {
                uint32_t ad = sb + (rA + mf * 16) * 64 + (((h * 2 + cA) ^ xA) << 4);
                LDMX4(a[mf][0], a[mf][1], a[mf][2], a[mf][3], ad);
            }
            #pragma unroll
            for (int nf = 0; nf < 4; nf++) {
                uint32_t bd = sb + 8192 + (rB + nf * 16) * 64 + (((h * 2 + cB) ^ xB) << 4);
                LDMX4(b[nf * 2][0], b[nf * 2][1], b[nf * 2 + 1][0], b[nf * 2 + 1][1], bd);
            }
            #pragma unroll
            for (int mf = 0; mf < 4; mf++)
                #pragma unroll
                for (int nf = 0; nf < 8; nf++)
                    MMA16816(acc[mf][nf], a[mf], b[nf]);
        }
    }

    // epilogue: direct register -> gmem with bias
    const int tr = lane >> 2;
    const int tc = (lane & 3) * 2;
    #pragma unroll
    for (int nf = 0; nf < 8; nf++) {
        const size_t col = bn + wn * 64 + nf * 8 + tc;
        const float bv0 = bias[col];
        const float bv1 = bias[col + 1];
        #pragma unroll
        for (int mf = 0; mf < 4; mf++) {
            const size_t row = bm + wm * 64 + mf * 16 + tr;
            float2 v0 = make_float2(acc[mf][nf][0] + bv0, acc[mf][nf][1] + bv1);
            float2 v1 = make_float2(acc[mf][nf][2] + bv0, acc[mf][nf][3] + bv1);
            *reinterpret_cast<float2*>(C + row * D_SAE + col)       = v0;
            *reinterpret_cast<float2*>(C + (row + 8) * D_SAE + col) = v1;
        }
    }
}

// ======================================================================
// Kernel 3: top-72 candidates per token (fp32 ranking, wide margin).
// ======================================================================
__global__ void topk_kernel(const float* __restrict__ pre,
                            float* __restrict__ sparse)
{
    extern __shared__ float sm[];
    float* vals = sm;
    float* rv   = sm + D_SAE;
    int*   ri   = reinterpret_cast<int*>(sm + D_SAE + 256);

    const int n = blockIdx.x;
    const int t = threadIdx.x;
    const float* row = pre + (size_t)n * D_SAE;
    float* srow = sparse + (size_t)n * D_SAE;

    for (int i = t; i < D_SAE; i += 256) {
        vals[i] = row[i];
        srow[i] = 0.0f;
    }
    __syncthreads();

    float myV = -FLT_MAX;
    int   myI = 0x7fffffff;
    bool rescan = true;

    for (int it = 0; it < K_CAND; it++) {
        if (rescan) {
            myV = -FLT_MAX; myI = 0x7fffffff;
            #pragma unroll 8
            for (int i = 0; i < D_SAE / 256; i++) {
                int idx = i * 256 + t;
                float v = vals[idx];
                if (v > myV) { myV = v; myI = idx; }
            }
            rescan = false;
        }
        rv[t] = myV; ri[t] = myI;
        __syncthreads();
        #pragma unroll
        for (int s = 128; s > 0; s >>= 1) {
            if (t < s) {
                float ov = rv[t + s]; int oi = ri[t + s];
                if (ov > rv[t] || (ov == rv[t] && oi < ri[t])) { rv[t] = ov; ri[t] = oi; }
            }
            __syncthreads();
        }
        int wi = ri[0];
        if (t == 0) {
            g_cand[n * K_CAND + it] = wi;
            vals[wi] = -FLT_MAX;
        }
        __syncthreads();
        if ((wi & 255) == t) rescan = true;
    }
}

// ======================================================================
// Kernel 4: refine + select (double-float exact ranking of 72 candidates)
// ======================================================================
__global__ __launch_bounds__(256)
void refine_kernel(const float* __restrict__ x,
                   const float* __restrict__ W_enc,
                   const float* __restrict__ b_enc,
                   const float* __restrict__ pre,
                   float* __restrict__ sparse)
{
    __shared__ float xs[D_MODEL];
    __shared__ float rh[256];
    __shared__ float rl[256];
    __shared__ float cvh[K_CAND];
    __shared__ float cvl[K_CAND];
    __shared__ int   cidx[K_CAND];

    const int n = blockIdx.x;
    const int t = threadIdx.x;

    #pragma unroll
    for (int j = 0; j < D_MODEL / 256; j++)
        xs[j * 256 + t] = x[(size_t)n * D_MODEL + j * 256 + t];
    if (t < K_CAND) cidx[t] = g_cand[n * K_CAND + t];
    __syncthreads();

    for (int c = 0; c < K_CAND; c++) {
        const int f = cidx[c];
        const float* wrow = W_enc + (size_t)f * D_MODEL;
        float hi = 0.0f, lo = 0.0f;
        #pragma unroll
        for (int j = 0; j < D_MODEL / 256; j++) {
            int k = j * 256 + t;
            float a = xs[k];
            float b = wrow[k];
            float p  = a * b;
            float ep = fmaf(a, b, -p);
            float s, e;
            two_sum(hi, p, s, e);
            hi = s;
            lo += (e + ep);
        }
        rh[t] = hi; rl[t] = lo;
        __syncthreads();
        #pragma unroll
        for (int s = 128; s > 0; s >>= 1) {
            if (t < s) {
                float h = rh[t], l = rl[t];
                df_add(h, l, rh[t + s], rl[t + s]);
                rh[t] = h; rl[t] = l;
            }
            __syncthreads();
        }
        if (t == 0) {
            float h = rh[0], l = rl[0];
            df_add(h, l, b_enc[f], 0.0f);
            cvh[c] = h; cvl[c] = l;
        }
        __syncthreads();
    }

    if (t < K_CAND) {
        float hI = cvh[t], lI = cvl[t];
        int   iI = cidx[t];
        int beats = 0;
        for (int j = 0; j < K_CAND; j++) {
            float hJ = cvh[j], lJ = cvl[j];
            int   iJ = cidx[j];
            bool gt = (hJ > hI) || (hJ == hI && (lJ > lI || (lJ == lI && iJ < iI)));
            beats += gt ? 1 : 0;
        }
        if (beats < K_SPARSE) {
            float v = pre[(size_t)n * D_SAE + iI];
            sparse[(size_t)n * D_SAE + iI] = v;
            g_tv[n * K_SPARSE + beats] = v;
            g_ti[n * K_SPARSE + beats] = iI;
        }
    }
}

// ======================================================================
// Kernel 5: sparse decode
// ======================================================================
__global__ __launch_bounds__(256)
void decode_kernel(const float* __restrict__ b_dec, float* __restrict__ recon)
{
    __shared__ float sval[K_SPARSE];
    __shared__ int   sidx[K_SPARSE];
    const int n = blockIdx.x;
    const int t = threadIdx.x;
    if (t < K_SPARSE) {
        sval[t] = g_tv[n * K_SPARSE + t];
        sidx[t] = g_ti[n * K_SPARSE + t];
    }
    __syncthreads();

    float4 acc[4];
    #pragma unroll
    for (int c = 0; c < 4; c++)
        acc[c] = *reinterpret_cast<const float4*>(b_dec + c * 1024 + t * 4);

    #pragma unroll 4
    for (int j = 0; j < K_SPARSE; j++) {
        const float v = sval[j];
        const float* wrow = g_WdT + (size_t)sidx[j] * D_MODEL;
        #pragma unroll
        for (int c = 0; c < 4; c++) {
            float4 w = *reinterpret_cast<const float4*>(wrow + c * 1024 + t * 4);
            acc[c].x += v * w.x; acc[c].y += v * w.y;
            acc[c].z += v * w.z; acc[c].w += v * w.w;
        }
    }
    float* orow = recon + (size_t)n * D_MODEL;
    #pragma unroll
    for (int c = 0; c < 4; c++)
        *reinterpret_cast<float4*>(orow + c * 1024 + t * 4) = acc[c];
}

// ======================================================================
// kernel_launch
// ======================================================================
extern "C" void kernel_launch(void* const* d_in, const int* in_sizes, int n_in,
                              void* d_out, int out_size)
{
    const float* x     = (const float*)d_in[0];
    const float* W_enc = (const float*)d_in[1];
    const float* b_enc = (const float*)d_in[2];
    const float* W_dec = (const float*)d_in[3];
    const float* b_dec = (const float*)d_in[4];

    float* out    = (float*)d_out;
    float* recon  = out;
    float* sparse = out + (size_t)N_TOKENS * D_MODEL;
    float* pre    = sparse + (size_t)N_TOKENS * D_SAE;

    // 0) fp16 conversions of x and W_enc
    cvt_x_kernel<<<(int)(((size_t)N_TOKENS * D_MODEL) / 1024), 256>>>(x);
    cvt_w_kernel<<<(int)(((size_t)D_SAE * D_MODEL) / 1024), 256>>>(W_enc);

    // 1) transpose W_dec for coalesced sparse-row gathers
    {
        dim3 tb(32, 8), tg(D_SAE / 32, D_MODEL / 32);
        transpose_kernel<<<tg, tb>>>(W_dec);
    }

    // 2) encoder GEMM (fp16 mma.sync, fp32 accum) -> pre_acts
    {
        int smem = NSTAGES * STAGE_SZ;   // 64 KB
        cudaFuncSetAttribute(enc_gemm_kernel, cudaFuncAttributeMaxDynamicSharedMemorySize, smem);
        int grid = (N_TOKENS / BM) * (D_SAE / BN);   // 64 * 128 = 8192
        enc_gemm_kernel<<<grid, 128, smem>>>(b_enc, pre);
    }

    // 3) top-72 candidates (fp16-GEMM rank, 170-sigma margin) + zero-fill sparse
    {
        int smem = D_SAE * (int)sizeof(float) + 256 * (int)sizeof(float) + 256 * (int)sizeof(int);
        cudaFuncSetAttribute(topk_kernel, cudaFuncAttributeMaxDynamicSharedMemorySize, smem);
        topk_kernel<<<N_TOKENS, 256, smem>>>(pre, sparse);
    }

    // 4) double-float refinement -> exact top-64 selection + scatter
    refine_kernel<<<N_TOKENS, 256>>>(x, W_enc, b_enc, pre, sparse);

    // 5) sparse decode -> reconstruction
    decode_kernel<<<N_TOKENS, 256>>>(b_dec, recon);
}